// round 13
// baseline (speedup 1.0000x reference)
#include <cuda_runtime.h>
#include <cuda_bf16.h>
#include <cstdint>
#include <cstddef>

#define S_LEN 4096
#define B_SZ  8
#define D_SZ  1024
#define M_TOT (B_SZ * S_LEN)
#define P2_CTAS 128
#define NWORK 20
#define NTILE 4096        // total 128x128 GEMM tiles (32 chunks x 128)

__device__ float g_gate[(size_t)M_TOT * D_SZ];
__device__ float g_proj[(size_t)M_TOT * D_SZ];
__device__ float g_state[2][B_SZ * D_SZ];
__device__ unsigned g_cnt[4];
__device__ unsigned g_chunk[32];
__device__ unsigned short g_xh[(size_t)M_TOT * D_SZ];
__device__ unsigned short g_xl[(size_t)M_TOT * D_SZ];
__device__ unsigned short g_wh[(size_t)2 * D_SZ * D_SZ];
__device__ unsigned short g_wl[(size_t)2 * D_SZ * D_SZ];

typedef unsigned long long u64;

__device__ __forceinline__ u64 ffma2(u64 a, u64 b, u64 c) {
    u64 d;
    asm("fma.rn.f32x2 %0, %1, %2, %3;" : "=l"(d) : "l"(a), "l"(b), "l"(c));
    return d;
}
__device__ __forceinline__ float2 u2f(u64 v) {
    float2 f;
    asm("mov.b64 {%0, %1}, %2;" : "=f"(f.x), "=f"(f.y) : "l"(v));
    return f;
}
__device__ __forceinline__ void mma16816(float* c, const unsigned* a,
                                         unsigned b0, unsigned b1) {
    asm("mma.sync.aligned.m16n8k16.row.col.f32.bf16.bf16.f32 "
        "{%0,%1,%2,%3}, {%4,%5,%6,%7}, {%8,%9}, {%0,%1,%2,%3};"
        : "+f"(c[0]), "+f"(c[1]), "+f"(c[2]), "+f"(c[3])
        : "r"(a[0]), "r"(a[1]), "r"(a[2]), "r"(a[3]), "r"(b0), "r"(b1));
}
__device__ __forceinline__ void ldsm4(unsigned* r, unsigned addr) {
    asm volatile("ldmatrix.sync.aligned.m8n8.x4.shared.b16 {%0,%1,%2,%3}, [%4];"
                 : "=r"(r[0]), "=r"(r[1]), "=r"(r[2]), "=r"(r[3]) : "r"(addr));
}
__device__ __forceinline__ void cpasync16(unsigned saddr, const void* gaddr) {
    asm volatile("cp.async.ca.shared.global [%0], [%1], 16;"
                 :: "r"(saddr), "l"(gaddr));
}
__device__ __forceinline__ unsigned smem_u32(const void* p) {
    unsigned r;
    asm("{ .reg .u64 t; cvta.to.shared.u64 t, %1; cvt.u32.u64 %0, t; }"
        : "=r"(r) : "l"(p));
    return r;
}
__device__ __forceinline__ unsigned ld_acq(const unsigned* p) {
    unsigned v;
    asm volatile("ld.acquire.gpu.global.u32 %0, [%1];" : "=r"(v) : "l"(p) : "memory");
    return v;
}
__device__ __forceinline__ void red_release_add(unsigned* p, unsigned v) {
    asm volatile("red.release.gpu.global.add.u32 [%0], %1;" :: "l"(p), "r"(v) : "memory");
}
__device__ __forceinline__ void pack_hilo(float x, float y,
                                          unsigned& h, unsigned& l) {
    __nv_bfloat16 hx = __float2bfloat16_rn(x);
    __nv_bfloat16 hy = __float2bfloat16_rn(y);
    __nv_bfloat16 lx = __float2bfloat16_rn(x - __bfloat162float(hx));
    __nv_bfloat16 ly = __float2bfloat16_rn(y - __bfloat162float(hy));
    h = (unsigned)__bfloat16_as_ushort(hx) | ((unsigned)__bfloat16_as_ushort(hy) << 16);
    l = (unsigned)__bfloat16_as_ushort(lx) | ((unsigned)__bfloat16_as_ushort(ly) << 16);
}

// ---------------------------------------------------------------------------
// Init: zero counters/state; convert x and W_in to bf16 hi/lo arrays.
// ---------------------------------------------------------------------------
#define NX4 ((size_t)M_TOT * D_SZ / 4)
#define NW4 ((size_t)2 * D_SZ * D_SZ / 4)
__global__ void init_convert(const float* __restrict__ X,
                             const float* __restrict__ Win) {
    size_t tid = (size_t)blockIdx.x * blockDim.x + threadIdx.x;
    size_t stride = (size_t)gridDim.x * blockDim.x;
    if (blockIdx.x == 0) {
        if (threadIdx.x < 4) g_cnt[threadIdx.x] = 0u;
        if (threadIdx.x < 32) g_chunk[threadIdx.x] = 0u;
        for (int i = threadIdx.x; i < B_SZ * D_SZ; i += blockDim.x)
            g_state[0][i] = 0.0f;
    }
    for (size_t i = tid; i < NX4; i += stride) {
        float4 v = ((const float4*)X)[i];
        uint2 h, l;
        pack_hilo(v.x, v.y, h.x, l.x);
        pack_hilo(v.z, v.w, h.y, l.y);
        ((uint2*)g_xh)[i] = h;
        ((uint2*)g_xl)[i] = l;
    }
    for (size_t i = tid; i < NW4; i += stride) {
        float4 v = ((const float4*)Win)[i];
        uint2 h, l;
        pack_hilo(v.x, v.y, h.x, l.x);
        pack_hilo(v.z, v.w, h.y, l.y);
        ((uint2*)g_wh)[i] = h;
        ((uint2*)g_wl)[i] = l;
    }
}

// ---------------------------------------------------------------------------
// GEMM tile (validated R10/R11): one 128x128 tile of z = X@Win^T + bin,
// bf16 hi/lo HMMA, ldmatrix, cp.async double-buffer.
// ---------------------------------------------------------------------------
#define SROW 20
#define BUFU (128 * SROW)
#define STGU (4 * BUFU)
#define P1_SMEM (2 * STGU * 4)   // 81920 B dynamic

__device__ __forceinline__ void stage_k(unsigned sm_base, unsigned stg,
                                        int m0, int n0, int k0, int tid) {
    const int buf = tid >> 6;
    const int t64 = tid & 63;
    const unsigned short* src = (buf == 0) ? g_xh : (buf == 1) ? g_xl
                              : (buf == 2) ? g_wh : g_wl;
    const int rb = (buf < 2) ? m0 : n0;
    #pragma unroll
    for (int j = 0; j < 8; ++j) {
        int cidx = t64 + 64 * j;
        int row = cidx >> 2;
        int c = cidx & 3;
        const void* g = src + (size_t)(rb + row) * D_SZ + k0 + 8 * c;
        unsigned s = sm_base + 4u * (stg + buf * BUFU + row * SROW + c * 4);
        cpasync16(s, g);
    }
}

__device__ void gemm_tile(unsigned sm_base, int m0, int n0,
                          const float* __restrict__ bin, int tid) {
    const int lane = tid & 31, w = tid >> 5;
    const int m_off = (w & 3) * 32;
    const int n_off = (w >> 2) * 64;
    const int ti = lane >> 3, lr = lane & 7;
    const int a_r = (ti & 1) * 8 + lr;
    const int a_k = (ti >> 1) * 4;
    const int b_r = (ti >> 1) * 8 + lr;
    const int b_k = (ti & 1) * 4;

    float C[2][8][4];
    #pragma unroll
    for (int mt = 0; mt < 2; ++mt)
        #pragma unroll
        for (int nt = 0; nt < 8; ++nt)
            #pragma unroll
            for (int q = 0; q < 4; ++q) C[mt][nt][q] = 0.0f;

    stage_k(sm_base, 0, m0, n0, 0, tid);
    asm volatile("cp.async.commit_group;" ::: "memory");

    for (int it = 0; it < 32; ++it) {
        if (it < 31) {
            stage_k(sm_base, ((it + 1) & 1) * STGU, m0, n0, 32 * (it + 1), tid);
            asm volatile("cp.async.commit_group;" ::: "memory");
            asm volatile("cp.async.wait_group 1;" ::: "memory");
        } else {
            asm volatile("cp.async.wait_group 0;" ::: "memory");
        }
        __syncthreads();

        const unsigned stg = (it & 1) * STGU;
        #pragma unroll
        for (int ks = 0; ks < 2; ++ks) {
            const int ku = ks * 8;
            unsigned ah[2][4], al[2][4];
            #pragma unroll
            for (int mt = 0; mt < 2; ++mt) {
                int row = m_off + mt * 16 + a_r;
                unsigned addr = sm_base + 4u * (stg + row * SROW + ku + a_k);
                ldsm4(ah[mt], addr);
                ldsm4(al[mt], addr + 4u * BUFU);
            }
            #pragma unroll
            for (int p = 0; p < 4; ++p) {
                int row = n_off + p * 16 + b_r;
                unsigned addr = sm_base + 4u * (stg + 2 * BUFU + row * SROW + ku + b_k);
                unsigned bh[4], bl[4];
                ldsm4(bh, addr);
                ldsm4(bl, addr + 4u * BUFU);
                #pragma unroll
                for (int mt = 0; mt < 2; ++mt) {
                    mma16816(C[mt][2 * p],     ah[mt], bh[0], bh[1]);
                    mma16816(C[mt][2 * p],     ah[mt], bl[0], bl[1]);
                    mma16816(C[mt][2 * p],     al[mt], bh[0], bh[1]);
                    mma16816(C[mt][2 * p + 1], ah[mt], bh[2], bh[3]);
                    mma16816(C[mt][2 * p + 1], ah[mt], bl[2], bl[3]);
                    mma16816(C[mt][2 * p + 1], al[mt], bh[2], bh[3]);
                }
            }
        }
        __syncthreads();
    }

    const int fr = lane >> 2, fc = lane & 3;
    const bool is_gate = (n0 < D_SZ);
    float* dst = is_gate ? g_gate : g_proj;
    const int csub = is_gate ? 0 : D_SZ;
    #pragma unroll
    for (int mt = 0; mt < 2; ++mt) {
        const int r = m0 + m_off + mt * 16 + fr;
        #pragma unroll
        for (int nt = 0; nt < 8; ++nt) {
            const int cn = n0 + n_off + nt * 8 + fc * 2;
            float b0 = bin[cn], b1 = bin[cn + 1];
            float v0 = C[mt][nt][0] + b0, v1 = C[mt][nt][1] + b1;
            float v2 = C[mt][nt][2] + b0, v3 = C[mt][nt][3] + b1;
            if (is_gate) {
                v0 = 1.0f / (1.0f + __expf(-v0));
                v1 = 1.0f / (1.0f + __expf(-v1));
                v2 = 1.0f / (1.0f + __expf(-v2));
                v3 = 1.0f / (1.0f + __expf(-v3));
            }
            *(float2*)&dst[(size_t)r * D_SZ + cn - csub]       = make_float2(v0, v1);
            *(float2*)&dst[(size_t)(r + 8) * D_SZ + cn - csub] = make_float2(v2, v3);
        }
    }
}

// ---------------------------------------------------------------------------
// Fused kernel: 148 CTAs, all co-resident (1/SM by reg usage).
//  blk <  128 : recurrence CTA (R11-proven scan, + per-chunk gate wait)
//  blk >= 128 : GEMM worker; strides chunk-major over 4096 tiles, releases
//               g_chunk[c] per tile. Chunk c = timesteps [128c, 128c+128).
// ---------------------------------------------------------------------------
__global__ __launch_bounds__(256, 1) void fused_kernel(
    const float* __restrict__ Ws, const float* __restrict__ bs,
    const float* __restrict__ bin, float* __restrict__ out)
{
    extern __shared__ unsigned smdyn[];

    if (blockIdx.x >= P2_CTAS) {
        // ---------------- GEMM worker ----------------
        const unsigned sm_base = smem_u32(smdyn);
        const int wk = blockIdx.x - P2_CTAS;
        const int tid = threadIdx.x;
        for (int tau = wk; tau < NTILE; tau += NWORK) {
            const int c = tau >> 7;            // chunk
            const int j = tau & 127;
            const int b = j >> 4;              // batch  (m-tile)
            const int n = j & 15;              // n-tile
            gemm_tile(sm_base, b * S_LEN + 128 * c, n * 128, bin, tid);
            __syncthreads();                   // all epilogue stores done
            if (tid == 0) red_release_add(&g_chunk[c], 1u);
        }
        return;
    }

    // ---------------- recurrence CTA (R11 structure) ----------------
    __shared__ float4 st4[512];

    const int tid   = threadIdx.x;
    const int lane  = tid & 31;
    const int w     = tid >> 5;
    const int blk   = blockIdx.x;
    const int grp   = blk >> 5;
    const int chunk = blk & 31;
    const int d0    = 32 * lane;

    u64 Wn[4][16];
    #pragma unroll
    for (int c = 0; c < 4; ++c) {
        const ulonglong2* wp =
            (const ulonglong2*)&Ws[(size_t)(chunk * 32 + 4 * w + c) * D_SZ + d0];
        #pragma unroll
        for (int q = 0; q < 8; ++q) {
            ulonglong2 v = wp[q];
            Wn[c][2 * q] = v.x; Wn[c][2 * q + 1] = v.y;
        }
    }

    const int ec   = chunk * 32 + 4 * w + (lane & 3);
    const int ebl  = (lane >> 2) & 1;
    const int eb   = 2 * grp + ebl;
    const float bsv = (lane < 8) ? bs[ec] : 0.0f;
    const int sf   = ebl * D_SZ + ec;
    const int sfp  = (((sf >> 2) ^ (((sf >> 2) >> 3) & 7)) << 2) | (sf & 3);

    unsigned* cnt = &g_cnt[grp];

    for (int t = 0; t < S_LEN; ++t) {
        // gate/proj chunk readiness (once per 128 steps; cold after startup)
        if ((t & 127) == 0) {
            const unsigned* cc = &g_chunk[t >> 7];
            while (ld_acq(cc) < 128u) __nanosleep(64);
        }

        float gv = 0.0f, pv = 0.0f;
        if (lane < 8) {
            size_t gi = ((size_t)eb * S_LEN + t) * D_SZ + ec;
            gv = __ldcg(&g_gate[gi]);
            pv = __ldcg(&g_proj[gi]);
        }

        if (tid == 0) {
            const unsigned target = (unsigned)(32 * t);
            while (ld_acq(cnt) < target) { }
        }
        __syncthreads();

        const float4* cur = (const float4*)&g_state[t & 1][grp * 2 * D_SZ];
        {
            int i0 = tid;
            int i1 = tid + 256;
            st4[i0 ^ ((i0 >> 3) & 7)] = __ldcg(&cur[i0]);
            st4[i1 ^ ((i1 >> 3) & 7)] = __ldcg(&cur[i1]);
        }
        __syncthreads();

        u64 ac[2][4];
        #pragma unroll
        for (int b = 0; b < 2; ++b)
            #pragma unroll
            for (int c = 0; c < 4; ++c) ac[b][c] = 0ull;

        #pragma unroll
        for (int b = 0; b < 2; ++b) {
            #pragma unroll
            for (int q = 0; q < 8; ++q) {
                int a = b * 256 + 8 * lane + q;
                ulonglong2 sv = *(const ulonglong2*)&st4[a ^ ((a >> 3) & 7)];
                #pragma unroll
                for (int c = 0; c < 4; ++c) {
                    ac[b][c] = ffma2(Wn[c][2 * q],     sv.x, ac[b][c]);
                    ac[b][c] = ffma2(Wn[c][2 * q + 1], sv.y, ac[b][c]);
                }
            }
        }

        float s[8];
        #pragma unroll
        for (int b = 0; b < 2; ++b)
            #pragma unroll
            for (int c = 0; c < 4; ++c) {
                float2 f = u2f(ac[b][c]);
                s[b * 4 + c] = f.x + f.y;
            }
        #pragma unroll
        for (int m = 16; m > 0; m >>= 1)
            #pragma unroll
            for (int i = 0; i < 8; ++i)
                s[i] += __shfl_xor_sync(0xffffffffu, s[i], m);

        if (lane < 8) {
            float mix  = s[lane] + bsv + pv;
            float sold = ((const float*)st4)[sfp];
            float nxt  = gv * mix + (1.0f - gv) * sold;
            __stcg(&g_state[(t + 1) & 1][eb * D_SZ + ec], nxt);
            out[((size_t)eb * S_LEN + t) * D_SZ + ec] = nxt;
        }
        __syncthreads();

        if (tid == 0) red_release_add(cnt, 1u);
    }
}

// ---------------------------------------------------------------------------
extern "C" void kernel_launch(void* const* d_in, const int* in_sizes, int n_in,
                              void* d_out, int out_size) {
    const float* x    = (const float*)d_in[0];
    const float* W_in = (const float*)d_in[1];
    const float* b_in = (const float*)d_in[2];
    const float* W_s  = (const float*)d_in[3];
    const float* b_s  = (const float*)d_in[4];
    float* out = (float*)d_out;

    cudaFuncSetAttribute(fused_kernel,
                         cudaFuncAttributeMaxDynamicSharedMemorySize, P1_SMEM);

    init_convert<<<4096, 256>>>(x, W_in);
    fused_kernel<<<P2_CTAS + NWORK, 256, P1_SMEM>>>(W_s, b_s, b_in, out);
}

// round 14
// speedup vs baseline: 1.1358x; 1.1358x over previous
#include <cuda_runtime.h>
#include <cuda_bf16.h>
#include <cstdint>
#include <cstddef>

#define S_LEN 4096
#define B_SZ  8
#define D_SZ  1024
#define M_TOT (B_SZ * S_LEN)
#define P2_CTAS 128
#define NWORK 20
#define PRECHUNK 12                       // chunks 0..11 done full-chip
#define WTILE ((32 - PRECHUNK) * 128)     // worker tiles (chunks 12..31)

__device__ float g_gate[(size_t)M_TOT * D_SZ];
__device__ float g_proj[(size_t)M_TOT * D_SZ];
__device__ float g_state[2][B_SZ * D_SZ];
__device__ unsigned g_cnt[4];
__device__ unsigned g_chunk[32];
__device__ unsigned short g_xh[(size_t)M_TOT * D_SZ];
__device__ unsigned short g_xl[(size_t)M_TOT * D_SZ];
__device__ unsigned short g_wh[(size_t)2 * D_SZ * D_SZ];
__device__ unsigned short g_wl[(size_t)2 * D_SZ * D_SZ];

typedef unsigned long long u64;

__device__ __forceinline__ u64 ffma2(u64 a, u64 b, u64 c) {
    u64 d;
    asm("fma.rn.f32x2 %0, %1, %2, %3;" : "=l"(d) : "l"(a), "l"(b), "l"(c));
    return d;
}
__device__ __forceinline__ float2 u2f(u64 v) {
    float2 f;
    asm("mov.b64 {%0, %1}, %2;" : "=f"(f.x), "=f"(f.y) : "l"(v));
    return f;
}
__device__ __forceinline__ void mma16816(float* c, const unsigned* a,
                                         unsigned b0, unsigned b1) {
    asm("mma.sync.aligned.m16n8k16.row.col.f32.bf16.bf16.f32 "
        "{%0,%1,%2,%3}, {%4,%5,%6,%7}, {%8,%9}, {%0,%1,%2,%3};"
        : "+f"(c[0]), "+f"(c[1]), "+f"(c[2]), "+f"(c[3])
        : "r"(a[0]), "r"(a[1]), "r"(a[2]), "r"(a[3]), "r"(b0), "r"(b1));
}
__device__ __forceinline__ void ldsm4(unsigned* r, unsigned addr) {
    asm volatile("ldmatrix.sync.aligned.m8n8.x4.shared.b16 {%0,%1,%2,%3}, [%4];"
                 : "=r"(r[0]), "=r"(r[1]), "=r"(r[2]), "=r"(r[3]) : "r"(addr));
}
__device__ __forceinline__ void cpasync16(unsigned saddr, const void* gaddr) {
    asm volatile("cp.async.ca.shared.global [%0], [%1], 16;"
                 :: "r"(saddr), "l"(gaddr));
}
__device__ __forceinline__ unsigned smem_u32(const void* p) {
    unsigned r;
    asm("{ .reg .u64 t; cvta.to.shared.u64 t, %1; cvt.u32.u64 %0, t; }"
        : "=r"(r) : "l"(p));
    return r;
}
__device__ __forceinline__ unsigned ld_acq(const unsigned* p) {
    unsigned v;
    asm volatile("ld.acquire.gpu.global.u32 %0, [%1];" : "=r"(v) : "l"(p) : "memory");
    return v;
}
__device__ __forceinline__ void red_release_add(unsigned* p, unsigned v) {
    asm volatile("red.release.gpu.global.add.u32 [%0], %1;" :: "l"(p), "r"(v) : "memory");
}
__device__ __forceinline__ void pack_hilo(float x, float y,
                                          unsigned& h, unsigned& l) {
    __nv_bfloat16 hx = __float2bfloat16_rn(x);
    __nv_bfloat16 hy = __float2bfloat16_rn(y);
    __nv_bfloat16 lx = __float2bfloat16_rn(x - __bfloat162float(hx));
    __nv_bfloat16 ly = __float2bfloat16_rn(y - __bfloat162float(hy));
    h = (unsigned)__bfloat16_as_ushort(hx) | ((unsigned)__bfloat16_as_ushort(hy) << 16);
    l = (unsigned)__bfloat16_as_ushort(lx) | ((unsigned)__bfloat16_as_ushort(ly) << 16);
}

// ---------------------------------------------------------------------------
// Init: zero counters/state; convert x, W_in to bf16 hi/lo arrays.
// ---------------------------------------------------------------------------
#define NX4 ((size_t)M_TOT * D_SZ / 4)
#define NW4 ((size_t)2 * D_SZ * D_SZ / 4)
__global__ void init_convert(const float* __restrict__ X,
                             const float* __restrict__ Win) {
    size_t tid = (size_t)blockIdx.x * blockDim.x + threadIdx.x;
    size_t stride = (size_t)gridDim.x * blockDim.x;
    if (blockIdx.x == 0) {
        if (threadIdx.x < 4) g_cnt[threadIdx.x] = 0u;
        if (threadIdx.x < 32)
            g_chunk[threadIdx.x] = (threadIdx.x < PRECHUNK) ? 128u : 0u;
        for (int i = threadIdx.x; i < B_SZ * D_SZ; i += blockDim.x)
            g_state[0][i] = 0.0f;
    }
    for (size_t i = tid; i < NX4; i += stride) {
        float4 v = ((const float4*)X)[i];
        uint2 h, l;
        pack_hilo(v.x, v.y, h.x, l.x);
        pack_hilo(v.z, v.w, h.y, l.y);
        ((uint2*)g_xh)[i] = h;
        ((uint2*)g_xl)[i] = l;
    }
    for (size_t i = tid; i < NW4; i += stride) {
        float4 v = ((const float4*)Win)[i];
        uint2 h, l;
        pack_hilo(v.x, v.y, h.x, l.x);
        pack_hilo(v.z, v.w, h.y, l.y);
        ((uint2*)g_wh)[i] = h;
        ((uint2*)g_wl)[i] = l;
    }
}

// ---------------------------------------------------------------------------
// GEMM tile body (validated R10-R13).
// ---------------------------------------------------------------------------
#define SROW 20
#define BUFU (128 * SROW)
#define STGU (4 * BUFU)
#define P1_SMEM (2 * STGU * 4)

__device__ __forceinline__ void stage_k(unsigned sm_base, unsigned stg,
                                        int m0, int n0, int k0, int tid) {
    const int buf = tid >> 6;
    const int t64 = tid & 63;
    const unsigned short* src = (buf == 0) ? g_xh : (buf == 1) ? g_xl
                              : (buf == 2) ? g_wh : g_wl;
    const int rb = (buf < 2) ? m0 : n0;
    #pragma unroll
    for (int j = 0; j < 8; ++j) {
        int cidx = t64 + 64 * j;
        int row = cidx >> 2;
        int c = cidx & 3;
        const void* g = src + (size_t)(rb + row) * D_SZ + k0 + 8 * c;
        unsigned s = sm_base + 4u * (stg + buf * BUFU + row * SROW + c * 4);
        cpasync16(s, g);
    }
}

__device__ void gemm_tile(unsigned sm_base, int m0, int n0,
                          const float* __restrict__ bin, int tid) {
    const int lane = tid & 31, w = tid >> 5;
    const int m_off = (w & 3) * 32;
    const int n_off = (w >> 2) * 64;
    const int ti = lane >> 3, lr = lane & 7;
    const int a_r = (ti & 1) * 8 + lr;
    const int a_k = (ti >> 1) * 4;
    const int b_r = (ti >> 1) * 8 + lr;
    const int b_k = (ti & 1) * 4;

    float C[2][8][4];
    #pragma unroll
    for (int mt = 0; mt < 2; ++mt)
        #pragma unroll
        for (int nt = 0; nt < 8; ++nt)
            #pragma unroll
            for (int q = 0; q < 4; ++q) C[mt][nt][q] = 0.0f;

    stage_k(sm_base, 0, m0, n0, 0, tid);
    asm volatile("cp.async.commit_group;" ::: "memory");

    for (int it = 0; it < 32; ++it) {
        if (it < 31) {
            stage_k(sm_base, ((it + 1) & 1) * STGU, m0, n0, 32 * (it + 1), tid);
            asm volatile("cp.async.commit_group;" ::: "memory");
            asm volatile("cp.async.wait_group 1;" ::: "memory");
        } else {
            asm volatile("cp.async.wait_group 0;" ::: "memory");
        }
        __syncthreads();

        const unsigned stg = (it & 1) * STGU;
        #pragma unroll
        for (int ks = 0; ks < 2; ++ks) {
            const int ku = ks * 8;
            unsigned ah[2][4], al[2][4];
            #pragma unroll
            for (int mt = 0; mt < 2; ++mt) {
                int row = m_off + mt * 16 + a_r;
                unsigned addr = sm_base + 4u * (stg + row * SROW + ku + a_k);
                ldsm4(ah[mt], addr);
                ldsm4(al[mt], addr + 4u * BUFU);
            }
            #pragma unroll
            for (int p = 0; p < 4; ++p) {
                int row = n_off + p * 16 + b_r;
                unsigned addr = sm_base + 4u * (stg + 2 * BUFU + row * SROW + ku + b_k);
                unsigned bh[4], bl[4];
                ldsm4(bh, addr);
                ldsm4(bl, addr + 4u * BUFU);
                #pragma unroll
                for (int mt = 0; mt < 2; ++mt) {
                    mma16816(C[mt][2 * p],     ah[mt], bh[0], bh[1]);
                    mma16816(C[mt][2 * p],     ah[mt], bl[0], bl[1]);
                    mma16816(C[mt][2 * p],     al[mt], bh[0], bh[1]);
                    mma16816(C[mt][2 * p + 1], ah[mt], bh[2], bh[3]);
                    mma16816(C[mt][2 * p + 1], ah[mt], bl[2], bl[3]);
                    mma16816(C[mt][2 * p + 1], al[mt], bh[2], bh[3]);
                }
            }
        }
        __syncthreads();
    }

    const int fr = lane >> 2, fc = lane & 3;
    const bool is_gate = (n0 < D_SZ);
    float* dst = is_gate ? g_gate : g_proj;
    const int csub = is_gate ? 0 : D_SZ;
    #pragma unroll
    for (int mt = 0; mt < 2; ++mt) {
        const int r = m0 + m_off + mt * 16 + fr;
        #pragma unroll
        for (int nt = 0; nt < 8; ++nt) {
            const int cn = n0 + n_off + nt * 8 + fc * 2;
            float b0 = bin[cn], b1 = bin[cn + 1];
            float v0 = C[mt][nt][0] + b0, v1 = C[mt][nt][1] + b1;
            float v2 = C[mt][nt][2] + b0, v3 = C[mt][nt][3] + b1;
            if (is_gate) {
                v0 = 1.0f / (1.0f + __expf(-v0));
                v1 = 1.0f / (1.0f + __expf(-v1));
                v2 = 1.0f / (1.0f + __expf(-v2));
                v3 = 1.0f / (1.0f + __expf(-v3));
            }
            *(float2*)&dst[(size_t)r * D_SZ + cn - csub]       = make_float2(v0, v1);
            *(float2*)&dst[(size_t)(r + 8) * D_SZ + cn - csub] = make_float2(v2, v3);
        }
    }
}

// ---------------------------------------------------------------------------
// Phase A: full-chip GEMM over chunks 0..PRECHUNK-1.
// grid (16, 8*PRECHUNK): by -> batch b = by/PRECHUNK, m-tile mt = by%PRECHUNK.
// ---------------------------------------------------------------------------
__global__ __launch_bounds__(256, 2) void phase1_prefix(
    const float* __restrict__ bin)
{
    extern __shared__ unsigned sm[];
    const unsigned sm_base = smem_u32(sm);
    const int b  = blockIdx.y / PRECHUNK;
    const int mt = blockIdx.y % PRECHUNK;
    gemm_tile(sm_base, b * S_LEN + 128 * mt, blockIdx.x * 128,
              bin, threadIdx.x);
}

// ---------------------------------------------------------------------------
// Fused kernel: 148 CTAs (1/SM).
//  blk <  128 : recurrence CTA — R11-proven scan + chunk gate (c>=PRECHUNK)
//  blk >= 128 : GEMM worker over chunks PRECHUNK..31
// ---------------------------------------------------------------------------
__global__ __launch_bounds__(256, 1) void fused_kernel(
    const float* __restrict__ Ws, const float* __restrict__ bs,
    const float* __restrict__ bin, float* __restrict__ out)
{
    extern __shared__ unsigned smdyn[];

    if (blockIdx.x >= P2_CTAS) {
        const unsigned sm_base = smem_u32(smdyn);
        const int wk = blockIdx.x - P2_CTAS;
        const int tid = threadIdx.x;
        for (int tau = wk; tau < WTILE; tau += NWORK) {
            const int c = PRECHUNK + (tau >> 7);
            const int j = tau & 127;
            const int b = j >> 4;
            const int n = j & 15;
            gemm_tile(sm_base, b * S_LEN + 128 * c, n * 128, bin, tid);
            __syncthreads();
            if (tid == 0) red_release_add(&g_chunk[c], 1u);
        }
        return;
    }

    // ---------------- recurrence CTA (R11 exact) ----------------
    __shared__ float4 st4[512];

    const int tid   = threadIdx.x;
    const int lane  = tid & 31;
    const int w     = tid >> 5;
    const int blk   = blockIdx.x;
    const int grp   = blk >> 5;
    const int chunk = blk & 31;
    const int d0    = 32 * lane;

    u64 Wn[4][16];
    #pragma unroll
    for (int c = 0; c < 4; ++c) {
        const ulonglong2* wp =
            (const ulonglong2*)&Ws[(size_t)(chunk * 32 + 4 * w + c) * D_SZ + d0];
        #pragma unroll
        for (int q = 0; q < 8; ++q) {
            ulonglong2 v = wp[q];
            Wn[c][2 * q] = v.x; Wn[c][2 * q + 1] = v.y;
        }
    }

    const int ec   = chunk * 32 + 4 * w + (lane & 3);
    const int ebl  = (lane >> 2) & 1;
    const int eb   = 2 * grp + ebl;
    const float bsv = (lane < 8) ? bs[ec] : 0.0f;
    const int sf   = ebl * D_SZ + ec;
    const int sfp  = (((sf >> 2) ^ (((sf >> 2) >> 3) & 7)) << 2) | (sf & 3);

    unsigned* cnt = &g_cnt[grp];

    for (int t = 0; t < S_LEN; ++t) {
        if ((t & 127) == 0 && (t >> 7) >= PRECHUNK) {
            const unsigned* cc = &g_chunk[t >> 7];
            while (ld_acq(cc) < 128u) __nanosleep(64);
        }

        float gv = 0.0f, pv = 0.0f;
        if (lane < 8) {
            size_t gi = ((size_t)eb * S_LEN + t) * D_SZ + ec;
            gv = __ldcg(&g_gate[gi]);
            pv = __ldcg(&g_proj[gi]);
        }

        if (tid == 0) {
            const unsigned target = (unsigned)(32 * t);
            while (ld_acq(cnt) < target) { }
        }
        __syncthreads();

        const float4* cur = (const float4*)&g_state[t & 1][grp * 2 * D_SZ];
        {
            int i0 = tid;
            int i1 = tid + 256;
            st4[i0 ^ ((i0 >> 3) & 7)] = __ldcg(&cur[i0]);
            st4[i1 ^ ((i1 >> 3) & 7)] = __ldcg(&cur[i1]);
        }
        __syncthreads();

        u64 ac[2][4];
        #pragma unroll
        for (int b = 0; b < 2; ++b)
            #pragma unroll
            for (int c = 0; c < 4; ++c) ac[b][c] = 0ull;

        #pragma unroll
        for (int b = 0; b < 2; ++b) {
            #pragma unroll
            for (int q = 0; q < 8; ++q) {
                int a = b * 256 + 8 * lane + q;
                ulonglong2 sv = *(const ulonglong2*)&st4[a ^ ((a >> 3) & 7)];
                #pragma unroll
                for (int c = 0; c < 4; ++c) {
                    ac[b][c] = ffma2(Wn[c][2 * q],     sv.x, ac[b][c]);
                    ac[b][c] = ffma2(Wn[c][2 * q + 1], sv.y, ac[b][c]);
                }
            }
        }

        float s[8];
        #pragma unroll
        for (int b = 0; b < 2; ++b)
            #pragma unroll
            for (int c = 0; c < 4; ++c) {
                float2 f = u2f(ac[b][c]);
                s[b * 4 + c] = f.x + f.y;
            }
        #pragma unroll
        for (int m = 16; m > 0; m >>= 1)
            #pragma unroll
            for (int i = 0; i < 8; ++i)
                s[i] += __shfl_xor_sync(0xffffffffu, s[i], m);

        if (lane < 8) {
            float mix  = s[lane] + bsv + pv;
            float sold = ((const float*)st4)[sfp];
            float nxt  = gv * mix + (1.0f - gv) * sold;
            __stcg(&g_state[(t + 1) & 1][eb * D_SZ + ec], nxt);
            out[((size_t)eb * S_LEN + t) * D_SZ + ec] = nxt;
        }
        __syncthreads();

        if (tid == 0) red_release_add(cnt, 1u);
    }
}

// ---------------------------------------------------------------------------
extern "C" void kernel_launch(void* const* d_in, const int* in_sizes, int n_in,
                              void* d_out, int out_size) {
    const float* x    = (const float*)d_in[0];
    const float* W_in = (const float*)d_in[1];
    const float* b_in = (const float*)d_in[2];
    const float* W_s  = (const float*)d_in[3];
    const float* b_s  = (const float*)d_in[4];
    float* out = (float*)d_out;

    cudaFuncSetAttribute(phase1_prefix,
                         cudaFuncAttributeMaxDynamicSharedMemorySize, P1_SMEM);
    cudaFuncSetAttribute(fused_kernel,
                         cudaFuncAttributeMaxDynamicSharedMemorySize, P1_SMEM);

    init_convert<<<4096, 256>>>(x, W_in);
    dim3 gA(16, 8 * PRECHUNK);
    phase1_prefix<<<gA, 256, P1_SMEM>>>(b_in);
    fused_kernel<<<P2_CTAS + NWORK, 256, P1_SMEM>>>(W_s, b_s, b_in, out);
}

// round 15
// speedup vs baseline: 1.1564x; 1.0182x over previous
#include <cuda_runtime.h>
#include <cuda_bf16.h>
#include <cstdint>
#include <cstddef>

#define S_LEN 4096
#define B_SZ  8
#define D_SZ  1024
#define M_TOT (B_SZ * S_LEN)
#define P2_CTAS 128
#define NWORK 20
#define PRECHUNK 10
#define WTILE ((32 - PRECHUNK) * 128)

__device__ float g_gate[(size_t)M_TOT * D_SZ];
__device__ float g_proj[(size_t)M_TOT * D_SZ];
__device__ float g_state[2][B_SZ * D_SZ];
__device__ unsigned g_cnt[4];
__device__ unsigned g_chunk[32];
__device__ unsigned short g_xh[(size_t)M_TOT * D_SZ];
__device__ unsigned short g_xl[(size_t)M_TOT * D_SZ];
__device__ unsigned short g_wh[(size_t)2 * D_SZ * D_SZ];
__device__ unsigned short g_wl[(size_t)2 * D_SZ * D_SZ];

typedef unsigned long long u64;

__device__ __forceinline__ u64 ffma2(u64 a, u64 b, u64 c) {
    u64 d;
    asm("fma.rn.f32x2 %0, %1, %2, %3;" : "=l"(d) : "l"(a), "l"(b), "l"(c));
    return d;
}
__device__ __forceinline__ float2 u2f(u64 v) {
    float2 f;
    asm("mov.b64 {%0, %1}, %2;" : "=f"(f.x), "=f"(f.y) : "l"(v));
    return f;
}
__device__ __forceinline__ void mma16816(float* c, const unsigned* a,
                                         unsigned b0, unsigned b1) {
    asm("mma.sync.aligned.m16n8k16.row.col.f32.bf16.bf16.f32 "
        "{%0,%1,%2,%3}, {%4,%5,%6,%7}, {%8,%9}, {%0,%1,%2,%3};"
        : "+f"(c[0]), "+f"(c[1]), "+f"(c[2]), "+f"(c[3])
        : "r"(a[0]), "r"(a[1]), "r"(a[2]), "r"(a[3]), "r"(b0), "r"(b1));
}
__device__ __forceinline__ void ldsm4(unsigned* r, unsigned addr) {
    asm volatile("ldmatrix.sync.aligned.m8n8.x4.shared.b16 {%0,%1,%2,%3}, [%4];"
                 : "=r"(r[0]), "=r"(r[1]), "=r"(r[2]), "=r"(r[3]) : "r"(addr));
}
__device__ __forceinline__ void cpasync16(unsigned saddr, const void* gaddr) {
    asm volatile("cp.async.ca.shared.global [%0], [%1], 16;"
                 :: "r"(saddr), "l"(gaddr));
}
__device__ __forceinline__ unsigned smem_u32(const void* p) {
    unsigned r;
    asm("{ .reg .u64 t; cvta.to.shared.u64 t, %1; cvt.u32.u64 %0, t; }"
        : "=r"(r) : "l"(p));
    return r;
}
__device__ __forceinline__ unsigned ld_acq(const unsigned* p) {
    unsigned v;
    asm volatile("ld.acquire.gpu.global.u32 %0, [%1];" : "=r"(v) : "l"(p) : "memory");
    return v;
}
__device__ __forceinline__ void red_release_add(unsigned* p, unsigned v) {
    asm volatile("red.release.gpu.global.add.u32 [%0], %1;" :: "l"(p), "r"(v) : "memory");
}
__device__ __forceinline__ void pack_hilo(float x, float y,
                                          unsigned& h, unsigned& l) {
    __nv_bfloat16 hx = __float2bfloat16_rn(x);
    __nv_bfloat16 hy = __float2bfloat16_rn(y);
    __nv_bfloat16 lx = __float2bfloat16_rn(x - __bfloat162float(hx));
    __nv_bfloat16 ly = __float2bfloat16_rn(y - __bfloat162float(hy));
    h = (unsigned)__bfloat16_as_ushort(hx) | ((unsigned)__bfloat16_as_ushort(hy) << 16);
    l = (unsigned)__bfloat16_as_ushort(lx) | ((unsigned)__bfloat16_as_ushort(ly) << 16);
}

// ---------------------------------------------------------------------------
// Init: zero counters/state; convert x, W_in to bf16 hi/lo arrays.
// ---------------------------------------------------------------------------
#define NX4 ((size_t)M_TOT * D_SZ / 4)
#define NW4 ((size_t)2 * D_SZ * D_SZ / 4)
__global__ void init_convert(const float* __restrict__ X,
                             const float* __restrict__ Win) {
    size_t tid = (size_t)blockIdx.x * blockDim.x + threadIdx.x;
    size_t stride = (size_t)gridDim.x * blockDim.x;
    if (blockIdx.x == 0) {
        if (threadIdx.x < 4) g_cnt[threadIdx.x] = 0u;
        if (threadIdx.x < 32)
            g_chunk[threadIdx.x] = (threadIdx.x < PRECHUNK) ? 128u : 0u;
        for (int i = threadIdx.x; i < B_SZ * D_SZ; i += blockDim.x)
            g_state[0][i] = 0.0f;
    }
    for (size_t i = tid; i < NX4; i += stride) {
        float4 v = ((const float4*)X)[i];
        uint2 h, l;
        pack_hilo(v.x, v.y, h.x, l.x);
        pack_hilo(v.z, v.w, h.y, l.y);
        ((uint2*)g_xh)[i] = h;
        ((uint2*)g_xl)[i] = l;
    }
    for (size_t i = tid; i < NW4; i += stride) {
        float4 v = ((const float4*)Win)[i];
        uint2 h, l;
        pack_hilo(v.x, v.y, h.x, l.x);
        pack_hilo(v.z, v.w, h.y, l.y);
        ((uint2*)g_wh)[i] = h;
        ((uint2*)g_wl)[i] = l;
    }
}

// ---------------------------------------------------------------------------
// GEMM tile body (validated R10-R14).
// ---------------------------------------------------------------------------
#define SROW 20
#define BUFU (128 * SROW)
#define STGU (4 * BUFU)
#define P1_SMEM (2 * STGU * 4)

__device__ __forceinline__ void stage_k(unsigned sm_base, unsigned stg,
                                        int m0, int n0, int k0, int tid) {
    const int buf = tid >> 6;
    const int t64 = tid & 63;
    const unsigned short* src = (buf == 0) ? g_xh : (buf == 1) ? g_xl
                              : (buf == 2) ? g_wh : g_wl;
    const int rb = (buf < 2) ? m0 : n0;
    #pragma unroll
    for (int j = 0; j < 8; ++j) {
        int cidx = t64 + 64 * j;
        int row = cidx >> 2;
        int c = cidx & 3;
        const void* g = src + (size_t)(rb + row) * D_SZ + k0 + 8 * c;
        unsigned s = sm_base + 4u * (stg + buf * BUFU + row * SROW + c * 4);
        cpasync16(s, g);
    }
}

__device__ void gemm_tile(unsigned sm_base, int m0, int n0,
                          const float* __restrict__ bin, int tid) {
    const int lane = tid & 31, w = tid >> 5;
    const int m_off = (w & 3) * 32;
    const int n_off = (w >> 2) * 64;
    const int ti = lane >> 3, lr = lane & 7;
    const int a_r = (ti & 1) * 8 + lr;
    const int a_k = (ti >> 1) * 4;
    const int b_r = (ti >> 1) * 8 + lr;
    const int b_k = (ti & 1) * 4;

    float C[2][8][4];
    #pragma unroll
    for (int mt = 0; mt < 2; ++mt)
        #pragma unroll
        for (int nt = 0; nt < 8; ++nt)
            #pragma unroll
            for (int q = 0; q < 4; ++q) C[mt][nt][q] = 0.0f;

    stage_k(sm_base, 0, m0, n0, 0, tid);
    asm volatile("cp.async.commit_group;" ::: "memory");

    for (int it = 0; it < 32; ++it) {
        if (it < 31) {
            stage_k(sm_base, ((it + 1) & 1) * STGU, m0, n0, 32 * (it + 1), tid);
            asm volatile("cp.async.commit_group;" ::: "memory");
            asm volatile("cp.async.wait_group 1;" ::: "memory");
        } else {
            asm volatile("cp.async.wait_group 0;" ::: "memory");
        }
        __syncthreads();

        const unsigned stg = (it & 1) * STGU;
        #pragma unroll
        for (int ks = 0; ks < 2; ++ks) {
            const int ku = ks * 8;
            unsigned ah[2][4], al[2][4];
            #pragma unroll
            for (int mt = 0; mt < 2; ++mt) {
                int row = m_off + mt * 16 + a_r;
                unsigned addr = sm_base + 4u * (stg + row * SROW + ku + a_k);
                ldsm4(ah[mt], addr);
                ldsm4(al[mt], addr + 4u * BUFU);
            }
            #pragma unroll
            for (int p = 0; p < 4; ++p) {
                int row = n_off + p * 16 + b_r;
                unsigned addr = sm_base + 4u * (stg + 2 * BUFU + row * SROW + ku + b_k);
                unsigned bh[4], bl[4];
                ldsm4(bh, addr);
                ldsm4(bl, addr + 4u * BUFU);
                #pragma unroll
                for (int mt = 0; mt < 2; ++mt) {
                    mma16816(C[mt][2 * p],     ah[mt], bh[0], bh[1]);
                    mma16816(C[mt][2 * p],     ah[mt], bl[0], bl[1]);
                    mma16816(C[mt][2 * p],     al[mt], bh[0], bh[1]);
                    mma16816(C[mt][2 * p + 1], ah[mt], bh[2], bh[3]);
                    mma16816(C[mt][2 * p + 1], ah[mt], bl[2], bl[3]);
                    mma16816(C[mt][2 * p + 1], al[mt], bh[2], bh[3]);
                }
            }
        }
        __syncthreads();
    }

    const int fr = lane >> 2, fc = lane & 3;
    const bool is_gate = (n0 < D_SZ);
    float* dst = is_gate ? g_gate : g_proj;
    const int csub = is_gate ? 0 : D_SZ;
    #pragma unroll
    for (int mt = 0; mt < 2; ++mt) {
        const int r = m0 + m_off + mt * 16 + fr;
        #pragma unroll
        for (int nt = 0; nt < 8; ++nt) {
            const int cn = n0 + n_off + nt * 8 + fc * 2;
            float b0 = bin[cn], b1 = bin[cn + 1];
            float v0 = C[mt][nt][0] + b0, v1 = C[mt][nt][1] + b1;
            float v2 = C[mt][nt][2] + b0, v3 = C[mt][nt][3] + b1;
            if (is_gate) {
                v0 = 1.0f / (1.0f + __expf(-v0));
                v1 = 1.0f / (1.0f + __expf(-v1));
                v2 = 1.0f / (1.0f + __expf(-v2));
                v3 = 1.0f / (1.0f + __expf(-v3));
            }
            *(float2*)&dst[(size_t)r * D_SZ + cn - csub]       = make_float2(v0, v1);
            *(float2*)&dst[(size_t)(r + 8) * D_SZ + cn - csub] = make_float2(v2, v3);
        }
    }
}

// ---------------------------------------------------------------------------
// Phase A: full-chip GEMM over chunks 0..PRECHUNK-1.
// ---------------------------------------------------------------------------
__global__ __launch_bounds__(256, 2) void phase1_prefix(
    const float* __restrict__ bin)
{
    extern __shared__ unsigned sm[];
    const unsigned sm_base = smem_u32(sm);
    const int b  = blockIdx.y / PRECHUNK;
    const int mt = blockIdx.y % PRECHUNK;
    gemm_tile(sm_base, b * S_LEN + 128 * mt, blockIdx.x * 128,
              bin, threadIdx.x);
}

// ---------------------------------------------------------------------------
// Fused kernel: 148 CTAs (1/SM).
//  blk <  128 : recurrence CTA — R11 sync skeleton + vectorized epilogue
//  blk >= 128 : GEMM worker over chunks PRECHUNK..31
// ---------------------------------------------------------------------------
__global__ __launch_bounds__(256, 1) void fused_kernel(
    const float* __restrict__ Ws, const float* __restrict__ bs,
    const float* __restrict__ bin, float* __restrict__ out)
{
    extern __shared__ unsigned smdyn[];

    if (blockIdx.x >= P2_CTAS) {
        const unsigned sm_base = smem_u32(smdyn);
        const int wk = blockIdx.x - P2_CTAS;
        const int tid = threadIdx.x;
        for (int tau = wk; tau < WTILE; tau += NWORK) {
            const int c = PRECHUNK + (tau >> 7);
            const int j = tau & 127;
            const int b = j >> 4;
            const int n = j & 15;
            gemm_tile(sm_base, b * S_LEN + 128 * c, n * 128, bin, tid);
            __syncthreads();
            if (tid == 0) red_release_add(&g_chunk[c], 1u);
        }
        return;
    }

    // ---------------- recurrence CTA ----------------
    __shared__ float4 st4[512];

    const int tid   = threadIdx.x;
    const int lane  = tid & 31;
    const int w     = tid >> 5;
    const int blk   = blockIdx.x;
    const int grp   = blk >> 5;
    const int chunk = blk & 31;
    const int d0    = 32 * lane;

    u64 Wn[4][16];
    #pragma unroll
    for (int c = 0; c < 4; ++c) {
        const ulonglong2* wp =
            (const ulonglong2*)&Ws[(size_t)(chunk * 32 + 4 * w + c) * D_SZ + d0];
        #pragma unroll
        for (int q = 0; q < 8; ++q) {
            ulonglong2 v = wp[q];
            Wn[c][2 * q] = v.x; Wn[c][2 * q + 1] = v.y;
        }
    }

    // vectorized epilogue (lanes 0..1): 4 contiguous cols per lane
    const int ec0 = chunk * 32 + 4 * w;          // first of this warp's 4 cols
    const int eb  = 2 * grp + lane;              // batch (valid for lane<2)
    float4 bsv4 = make_float4(0.f, 0.f, 0.f, 0.f);
    if (lane < 2) bsv4 = *(const float4*)&bs[ec0];
    // swizzled f4 index of old-state float4 (lane = local batch)
    const int sa  = lane * 256 + chunk * 8 + w;
    const int sp  = sa ^ ((sa >> 3) & 7);

    unsigned* cnt = &g_cnt[grp];

    for (int t = 0; t < S_LEN; ++t) {
        if ((t & 127) == 0 && (t >> 7) >= PRECHUNK) {
            const unsigned* cc = &g_chunk[t >> 7];
            while (ld_acq(cc) < 128u) __nanosleep(64);
        }

        // prefetch gate/proj (float4, lanes 0..1)
        float4 gv4, pv4;
        if (lane < 2) {
            size_t gi = ((size_t)eb * S_LEN + t) * D_SZ + ec0;
            gv4 = __ldcg((const float4*)&g_gate[gi]);
            pv4 = __ldcg((const float4*)&g_proj[gi]);
        }

        if (tid == 0) {
            const unsigned target = (unsigned)(32 * t);
            while (ld_acq(cnt) < target) { }
        }
        __syncthreads();

        const float4* cur = (const float4*)&g_state[t & 1][grp * 2 * D_SZ];
        {
            int i0 = tid;
            int i1 = tid + 256;
            st4[i0 ^ ((i0 >> 3) & 7)] = __ldcg(&cur[i0]);
            st4[i1 ^ ((i1 >> 3) & 7)] = __ldcg(&cur[i1]);
        }
        __syncthreads();

        u64 ac[2][4];
        #pragma unroll
        for (int b = 0; b < 2; ++b)
            #pragma unroll
            for (int c = 0; c < 4; ++c) ac[b][c] = 0ull;

        #pragma unroll
        for (int b = 0; b < 2; ++b) {
            #pragma unroll
            for (int q = 0; q < 8; ++q) {
                int a = b * 256 + 8 * lane + q;
                ulonglong2 sv = *(const ulonglong2*)&st4[a ^ ((a >> 3) & 7)];
                #pragma unroll
                for (int c = 0; c < 4; ++c) {
                    ac[b][c] = ffma2(Wn[c][2 * q],     sv.x, ac[b][c]);
                    ac[b][c] = ffma2(Wn[c][2 * q + 1], sv.y, ac[b][c]);
                }
            }
        }

        float s[8];
        #pragma unroll
        for (int b = 0; b < 2; ++b)
            #pragma unroll
            for (int c = 0; c < 4; ++c) {
                float2 f = u2f(ac[b][c]);
                s[b * 4 + c] = f.x + f.y;
            }
        #pragma unroll
        for (int m = 16; m > 0; m >>= 1)
            #pragma unroll
            for (int i = 0; i < 8; ++i)
                s[i] += __shfl_xor_sync(0xffffffffu, s[i], m);

        // vectorized gated epilogue (lanes 0..1)
        float4 nx;
        if (lane < 2) {
            float4 vsum = (lane == 0)
                        ? make_float4(s[0], s[1], s[2], s[3])
                        : make_float4(s[4], s[5], s[6], s[7]);
            float4 sold = st4[sp];
            nx.x = gv4.x * (vsum.x + bsv4.x + pv4.x) + (1.0f - gv4.x) * sold.x;
            nx.y = gv4.y * (vsum.y + bsv4.y + pv4.y) + (1.0f - gv4.y) * sold.y;
            nx.z = gv4.z * (vsum.z + bsv4.z + pv4.z) + (1.0f - gv4.z) * sold.z;
            nx.w = gv4.w * (vsum.w + bsv4.w + pv4.w) + (1.0f - gv4.w) * sold.w;
            __stcg((float4*)&g_state[(t + 1) & 1][eb * D_SZ + ec0], nx);
        }
        __syncthreads();

        if (tid == 0) red_release_add(cnt, 1u);

        // out store off the release path (overlaps next poll)
        if (lane < 2)
            *(float4*)&out[((size_t)eb * S_LEN + t) * D_SZ + ec0] = nx;
    }
}

// ---------------------------------------------------------------------------
extern "C" void kernel_launch(void* const* d_in, const int* in_sizes, int n_in,
                              void* d_out, int out_size) {
    const float* x    = (const float*)d_in[0];
    const float* W_in = (const float*)d_in[1];
    const float* b_in = (const float*)d_in[2];
    const float* W_s  = (const float*)d_in[3];
    const float* b_s  = (const float*)d_in[4];
    float* out = (float*)d_out;

    cudaFuncSetAttribute(phase1_prefix,
                         cudaFuncAttributeMaxDynamicSharedMemorySize, P1_SMEM);
    cudaFuncSetAttribute(fused_kernel,
                         cudaFuncAttributeMaxDynamicSharedMemorySize, P1_SMEM);

    init_convert<<<4096, 256>>>(x, W_in);
    dim3 gA(16, 8 * PRECHUNK);
    phase1_prefix<<<gA, 256, P1_SMEM>>>(b_in);
    fused_kernel<<<P2_CTAS + NWORK, 256, P1_SMEM>>>(W_s, b_s, b_in, out);
}